// round 17
// baseline (speedup 1.0000x reference)
#include <cuda_runtime.h>
#include <cuda_bf16.h>
#include <math.h>
#include <stdint.h>

// ---------------------------------------------------------------------------
// HungarianContrastiveLoss on GB300 (sm_103 base-ISA tensor cores)
//   sim = (O/0.05) @ [P;Ng]^T   (4096 x 8192, K=1024)
//   loss = mean_r( LSE(sim[r,:]) - sim[r, hungarian_col(r)] )
//
//   K0 convert: fp32 -> bf16 copies of O and E=[P;Ng]  (2-way MLP)
//   K1 fused:   bids 0..31    : 8 batches per CTA — diag 16x16 blocks + 8
//                               concurrent warp-JVs -> g_matched (+done flag)
//               bids 32..2079 : bf16 mma.sync GEMM (128x128 tile, 3-stage
//                               cp.async) + streaming base-2 LSE partials.
//                               The 64th finishing CTA of each row block
//                               finalizes its 128 rows; the 32nd finalizer
//                               emits the scalar loss. No finalize kernel.
// ---------------------------------------------------------------------------

#define NROWS  4096
#define NCOLSS 8192
#define DIM    1024
#define NTILE  64            // 8192 / 128 column tiles
#define SCALE  20.0f
#define C1     28.853900817779268f   // 20 * log2(e)
#define LN2f   0.6931471805599453f

#define BM 128
#define BN 128
#define BK 32
#define PITCH 40             // halves per SMEM row (80 B: 5 mod 8 -> no LDSM conflicts)

#define STAGE_A  (BM * PITCH * 2)          // 10240 B
#define STAGE_B  (BN * PITCH * 2)          // 10240 B
#define STAGE_SZ (STAGE_A + STAGE_B)       // 20480 B
#define NSTAGES  3
#define SMEM_DYN (NSTAGES * STAGE_SZ)      // 61440 B

#define DIAG_CTAS 32                       // 8 batches per CTA
#define GEMM_CTAS (NTILE * (NROWS / BM))   // 2048
#define TOTAL_CTAS (GEMM_CTAS + DIAG_CTAS)

// device-global scratch (allocation-free rule)
__device__ __nv_bfloat16 g_Obf[NROWS * DIM];
__device__ __nv_bfloat16 g_Ebf[NCOLSS * DIM];   // rows 0..4095 = P, 4096..8191 = Ng
__device__ float g_pmax[NTILE * NROWS];
__device__ float g_psum[NTILE * NROWS];
__device__ float g_matched[NROWS];
__device__ float g_partial[32];
__device__ unsigned g_tilecnt[32];              // per row-block tile completions
__device__ unsigned g_diagdone[32];             // per diag-CTA done flags
__device__ unsigned g_fincnt;                   // finalizer completions

// ---------------------------------------------------------------------------
// helpers
// ---------------------------------------------------------------------------
__device__ __forceinline__ uint32_t smem_u32(const void* p) {
    uint32_t a;
    asm("{ .reg .u64 t; cvta.to.shared.u64 t, %1; cvt.u32.u64 %0, t; }" : "=r"(a) : "l"(p));
    return a;
}
__device__ __forceinline__ void cp16(uint32_t dst, const void* src) {
    asm volatile("cp.async.cg.shared.global [%0], [%1], 16;" :: "r"(dst), "l"(src));
}
__device__ __forceinline__ float ex2f(float x) {
    float y; asm("ex2.approx.f32 %0, %1;" : "=f"(y) : "f"(x)); return y;
}
__device__ __forceinline__ float lg2f(float x) {
    float y; asm("lg2.approx.f32 %0, %1;" : "=f"(y) : "f"(x)); return y;
}
// order-preserving float <-> uint (for redux.sync.min on floats)
__device__ __forceinline__ unsigned ordf(float f) {
    unsigned u = __float_as_uint(f);
    return (u & 0x80000000u) ? ~u : (u | 0x80000000u);
}
__device__ __forceinline__ float unordf(unsigned u) {
    u = (u & 0x80000000u) ? (u & 0x7FFFFFFFu) : ~u;
    return __uint_as_float(u);
}
#define LDSM4(R0, R1, R2, R3, ADDR)                                             \
    asm volatile("ldmatrix.sync.aligned.m8n8.x4.shared.b16 {%0,%1,%2,%3}, [%4];"\
                 : "=r"(R0), "=r"(R1), "=r"(R2), "=r"(R3) : "r"(ADDR))

#define MMA_BF16(D, A, B0, B1)                                                  \
    asm volatile("mma.sync.aligned.m16n8k16.row.col.f32.bf16.bf16.f32 "         \
                 "{%0,%1,%2,%3}, {%4,%5,%6,%7}, {%8,%9}, {%0,%1,%2,%3};"        \
                 : "+f"((D)[0]), "+f"((D)[1]), "+f"((D)[2]), "+f"((D)[3])       \
                 : "r"((A)[0]), "r"((A)[1]), "r"((A)[2]), "r"((A)[3]),          \
                   "r"(B0), "r"(B1))

// ---------------------------------------------------------------------------
// Kernel 0: fp32 -> bf16 conversion. 2 independent float4 per thread (MLP=2).
// ---------------------------------------------------------------------------
__global__ __launch_bounds__(256) void convert_kernel(
    const float4* __restrict__ O, const float4* __restrict__ P,
    const float4* __restrict__ Ng)
{
    const int N4 = NROWS * DIM / 4;   // per tensor (1,048,576)
    uint2* ob = (uint2*)g_Obf;
    uint2* eb = (uint2*)g_Ebf;
    const int base = (blockIdx.x * 256 + threadIdx.x) * 2;
#pragma unroll
    for (int q = 0; q < 2; q++) {
        const int i = base + q;
        if (i >= 3 * N4) break;
        const float4* src; uint2* dst;
        if (i < N4)           { src = O + i;            dst = ob + i; }
        else if (i < 2 * N4)  { int j = i - N4;         src = P + j;  dst = eb + j; }
        else                  { int j = i - 2 * N4;     src = Ng + j; dst = eb + N4 + j; }
        float4 v;
        asm volatile("ld.global.nc.v4.f32 {%0,%1,%2,%3}, [%4];"
                     : "=f"(v.x), "=f"(v.y), "=f"(v.z), "=f"(v.w) : "l"(src));
        __nv_bfloat162 lo = __float22bfloat162_rn(make_float2(v.x, v.y));
        __nv_bfloat162 hi = __float22bfloat162_rn(make_float2(v.z, v.w));
        asm volatile("st.global.cs.v2.b32 [%0], {%1,%2};"
                     :: "l"(dst), "r"(*(uint32_t*)&lo), "r"(*(uint32_t*)&hi));
    }
}

// ---------------------------------------------------------------------------
// GEMM tile path (bids 32..2079 -> tile id 0..2047)
// ---------------------------------------------------------------------------
__device__ __forceinline__ void issue_chunk(
    const __nv_bfloat16* __restrict__ Ab, const __nv_bfloat16* __restrict__ Bb,
    uint32_t sA, uint32_t sB, int chunk, int tid)
{
    const int gk = chunk * BK;
#pragma unroll
    for (int it = 0; it < 2; it++) {
        int idx = it * 256 + tid;          // 0..511
        int r = idx >> 2;                  // row 0..127
        int q = idx & 3;                   // 8-half quarter
        cp16(sA + r * (PITCH * 2) + q * 16, Ab + (size_t)r * DIM + gk + q * 8);
        cp16(sB + r * (PITCH * 2) + q * 16, Bb + (size_t)r * DIM + gk + q * 8);
    }
}

__device__ void gemm_path(uint8_t* smem, int bid, float* __restrict__ out)
{
    const int tid  = threadIdx.x;
    const int lane = tid & 31;
    const int wid  = tid >> 5;
    const int wm   = wid & 3;      // 0..3 (m)
    const int wn   = wid >> 2;     // 0..1 (n)
    const int bn = bid & (NTILE - 1);
    const int bm = bid >> 6;

    const __nv_bfloat16* Ab = g_Obf + (size_t)bm * BM * DIM;
    const __nv_bfloat16* Bb = g_Ebf + (size_t)bn * BN * DIM;

    const uint32_t s0 = smem_u32(smem);

    const uint32_t aRow = (uint32_t)(wm * 32 + (lane & 7) + ((lane >> 3) & 1) * 8);
    const uint32_t aCol = (uint32_t)((lane >> 4) * 8);
    const uint32_t bRow = (uint32_t)(wn * 64 + (lane & 7) + (lane >> 4) * 8);
    const uint32_t bCol = (uint32_t)(((lane >> 3) & 1) * 8);

    float acc[2][8][4];
#pragma unroll
    for (int mt = 0; mt < 2; mt++)
#pragma unroll
        for (int nt = 0; nt < 8; nt++)
#pragma unroll
            for (int k = 0; k < 4; k++) acc[mt][nt][k] = 0.f;

    // prologue: chunks 0,1 into stages 0,1
    issue_chunk(Ab, Bb, s0, s0 + STAGE_A, 0, tid);
    asm volatile("cp.async.commit_group;" ::: "memory");
    issue_chunk(Ab, Bb, s0 + STAGE_SZ, s0 + STAGE_SZ + STAGE_A, 1, tid);
    asm volatile("cp.async.commit_group;" ::: "memory");

    int st_comp = 0;   // stage of chunk c
    int st_iss  = 2;   // stage of chunk c+2

    for (int c = 0; c < DIM / BK; c++) {
        if (c < DIM / BK - 1) {
            asm volatile("cp.async.wait_group 1;" ::: "memory");
        } else {
            asm volatile("cp.async.wait_group 0;" ::: "memory");
        }
        __syncthreads();

        if (c + 2 < DIM / BK) {
            uint32_t sb = s0 + st_iss * STAGE_SZ;
            issue_chunk(Ab, Bb, sb, sb + STAGE_A, c + 2, tid);
            asm volatile("cp.async.commit_group;" ::: "memory");
        }

        const uint32_t baseA = s0 + st_comp * STAGE_SZ;
        const uint32_t baseB = baseA + STAGE_A;
#pragma unroll
        for (int ks = 0; ks < 2; ks++) {
            const uint32_t kb = (uint32_t)(ks * 16);
            uint32_t a[2][4];
#pragma unroll
            for (int mt = 0; mt < 2; mt++) {
                uint32_t addr = baseA + (aRow + mt * 16) * (PITCH * 2) + (kb + aCol) * 2;
                LDSM4(a[mt][0], a[mt][1], a[mt][2], a[mt][3], addr);
            }
            uint32_t b[4][4];
#pragma unroll
            for (int nq = 0; nq < 4; nq++) {
                uint32_t addr = baseB + (bRow + nq * 16) * (PITCH * 2) + (kb + bCol) * 2;
                LDSM4(b[nq][0], b[nq][1], b[nq][2], b[nq][3], addr);
            }
#pragma unroll
            for (int mt = 0; mt < 2; mt++)
#pragma unroll
                for (int nt = 0; nt < 8; nt++)
                    MMA_BF16(acc[mt][nt], a[mt], b[nt >> 1][(nt & 1) * 2],
                             b[nt >> 1][(nt & 1) * 2 + 1]);
        }
        if (++st_comp == NSTAGES) st_comp = 0;
        if (++st_iss  == NSTAGES) st_iss  = 0;
    }

    // ---- epilogue: per-row base-2 LSE over this 128-col tile ----
    float2* part = (float2*)smem;

#pragma unroll
    for (int mt = 0; mt < 2; mt++) {
#pragma unroll
        for (int hf = 0; hf < 2; hf++) {
            float m = -1e30f;
            float e[16];
#pragma unroll
            for (int nt = 0; nt < 8; nt++) {
                e[nt * 2 + 0] = acc[mt][nt][hf * 2 + 0] * C1;
                e[nt * 2 + 1] = acc[mt][nt][hf * 2 + 1] * C1;
                m = fmaxf(m, fmaxf(e[nt * 2], e[nt * 2 + 1]));
            }
            float s = 0.f;
#pragma unroll
            for (int k = 0; k < 16; k++) s += ex2f(e[k] - m);
#pragma unroll
            for (int off = 1; off <= 2; off <<= 1) {
                float om = __shfl_xor_sync(0xffffffffu, m, off);
                float os = __shfl_xor_sync(0xffffffffu, s, off);
                float nm = fmaxf(m, om);
                s = s * ex2f(m - nm) + os * ex2f(om - nm);
                m = nm;
            }
            if ((lane & 3) == 0) {
                int row = wm * 32 + mt * 16 + hf * 8 + (lane >> 2);
                part[wn * 128 + row] = make_float2(m, s);
            }
        }
    }
    __syncthreads();
    if (tid < 128) {
        float2 p0 = part[tid];
        float2 p1 = part[128 + tid];
        float M = fmaxf(p0.x, p1.x);
        float S = p0.y * ex2f(p0.x - M) + p1.y * ex2f(p1.x - M);
        const int row = bm * BM + tid;
        g_pmax[bn * NROWS + row] = M;
        g_psum[bn * NROWS + row] = S;
    }

    // ---- completion protocol: 64th tile of this row block finalizes it ----
    __syncthreads();
    unsigned* sflag = (unsigned*)(smem + 2048);
    if (tid == 0) {
        __threadfence();
        sflag[0] = atomicAdd(&g_tilecnt[bm], 1u);
    }
    __syncthreads();
    if (sflag[0] != NTILE - 1) return;

    // wait for this row block's matched values (diag CTA bm, wave-1 resident)
    if (tid == 0) {
        while (((volatile unsigned*)g_diagdone)[bm] == 0) {}
        __threadfence();
    }
    __syncthreads();

    float* lossbuf = (float*)smem;
    if (tid < 128) {
        const int row = bm * BM + tid;
        float M = -1e30f;
#pragma unroll 8
        for (int t = 0; t < NTILE; t++) M = fmaxf(M, g_pmax[t * NROWS + row]);
        float S = 0.f;
#pragma unroll 8
        for (int t = 0; t < NTILE; t++)
            S += g_psum[t * NROWS + row] * ex2f(g_pmax[t * NROWS + row] - M);
        lossbuf[tid] = LN2f * (M + lg2f(S)) - g_matched[row];
    }
    __syncthreads();
    for (int s = 64; s; s >>= 1) {
        if (tid < s) lossbuf[tid] += lossbuf[tid + s];
        __syncthreads();
    }
    if (tid == 0) {
        g_partial[bm] = lossbuf[0];
        g_tilecnt[bm] = 0;          // reset for next graph replay
        g_diagdone[bm] = 0;
        __threadfence();
        unsigned old = atomicAdd(&g_fincnt, 1u);
        if (old == 31) {
            __threadfence();
            float s = 0.f;
#pragma unroll
            for (int i = 0; i < 32; i++) s += g_partial[i];
            out[0] = s * (1.0f / (float)NROWS);
            g_fincnt = 0;
        }
    }
}

// ---------------------------------------------------------------------------
// diag + Hungarian path, 8 BATCHES PER CTA (bids 0..31).
// ---------------------------------------------------------------------------
__device__ void diag_jv_path(const float* __restrict__ O, const float* __restrict__ P,
                             int cta, uint8_t* smem)
{
    float* so   = (float*)smem;                 // [16][257]  16448 B
    float* sp   = (float*)(smem + 16448);       // [16][257]  16448 B
    float* blk8 = (float*)(smem + 32896);       // [8][256]    8192 B
    float* su   = (float*)(smem + 41088);       // [8][17]      544 B
    int*   spp  = (int*)  (smem + 41632);       // [8][17]      544 B
    int*   swy  = (int*)  (smem + 42176);       // [8][17]      544 B

    const int tid = threadIdx.x;
    const int ti = tid >> 4;
    const int tj = tid & 15;

    // ---- phase 1: 8 diagonal blocks, cooperative, sequential ----
    for (int bb = 0; bb < 8; bb++) {
        const int b = cta * 8 + bb;
        float acc = 0.f;
        for (int k0 = 0; k0 < DIM; k0 += 256) {
            for (int t = tid; t < 16 * 256; t += 256) {
                int r = t >> 8, c = t & 255;
                so[r * 257 + c] = O[(size_t)(b * 16 + r) * DIM + k0 + c];
                sp[r * 257 + c] = P[(size_t)(b * 16 + r) * DIM + k0 + c];
            }
            __syncthreads();
#pragma unroll 8
            for (int k = 0; k < 256; k++) acc += so[ti * 257 + k] * sp[tj * 257 + k];
            __syncthreads();
        }
        blk8[bb * 256 + tid] = acc * SCALE;
    }
    __syncthreads();

    // ---- phase 2: 8 concurrent warp-JVs ----
    const int w    = tid >> 5;       // batch within CTA
    const int lane = tid & 31;
    const int b    = cta * 8 + w;
    float* blk = &blk8[w * 256];
    float* uS  = &su [w * 17];
    int*   pS  = &spp[w * 17];
    int*   wS  = &swy[w * 17];

    if (lane < 17) { uS[lane] = 0.f; pS[lane] = 0; }
    float v = 0.f;                 // lane<16: potential of column lane+1
    __syncwarp();

    for (int ii = 1; ii <= 16; ii++) {
        if (lane == 0) pS[0] = ii;
        float minv = 1e30f;
        int   wayr = 0;
        unsigned used = 0u;
        int j0 = 0;
        __syncwarp();

        for (int guard = 0; guard <= 16; guard++) {
            used |= (1u << j0);
            const int i0  = pS[j0];
            const float ui0 = uS[i0];

            bool act = (lane < 16) && !((used >> (lane + 1)) & 1u);
            if (act) {
                float cur = -blk[(i0 - 1) * 16 + lane] - ui0 - v;
                if (cur < minv) { minv = cur; wayr = j0; }
            }
            unsigned ou = act ? ordf(minv) : 0xFFFFFFFFu;
            unsigned mn = __reduce_min_sync(0xffffffffu, ou);
            unsigned bl = __ballot_sync(0xffffffffu, ou == mn);
            int   jm = __ffs(bl);          // winner lane + 1 == column index
            float d  = unordf(mn);

            if (lane < 16) {
                if ((used >> (lane + 1)) & 1u) { v -= d; uS[pS[lane + 1]] += d; }
                else                           { minv -= d; }
            } else if (lane == 16) {
                uS[pS[0]] += d;            // virtual column 0 always used
            }
            __syncwarp();
            j0 = jm;
            if (pS[j0] == 0) break;
        }

        if (lane < 16) wS[lane + 1] = wayr;
        __syncwarp();
        if (lane == 0) {
            int jj = j0;
            while (jj) { int j1 = wS[jj]; pS[jj] = pS[j1]; jj = j1; }
        }
        __syncwarp();
    }

    if (lane < 16) {
        const int row = pS[lane + 1] - 1;   // row matched to column lane
        g_matched[b * 16 + row] = blk[row * 16 + lane];
    }

    // signal: this CTA's 8 batches of g_matched are ready
    __syncthreads();
    if (tid == 0) {
        __threadfence();
        atomicExch(&g_diagdone[cta], 1u);
    }
}

// ---------------------------------------------------------------------------
// Kernel 1: fused diag/JV (first, 32 CTAs) + GEMM (+ inline finalize).
// ---------------------------------------------------------------------------
__global__ __launch_bounds__(256) void fused_kernel(
    const float* __restrict__ O, const float* __restrict__ P,
    float* __restrict__ out)
{
    extern __shared__ __align__(16) uint8_t dynsmem[];
    if (blockIdx.x < DIAG_CTAS) diag_jv_path(O, P, blockIdx.x, dynsmem);
    else                        gemm_path(dynsmem, blockIdx.x - DIAG_CTAS, out);
}

// ---------------------------------------------------------------------------
extern "C" void kernel_launch(void* const* d_in, const int* in_sizes, int n_in,
                              void* d_out, int out_size)
{
    const float* O  = (const float*)d_in[0];
    const float* P  = (const float*)d_in[1];
    const float* Ng = (const float*)d_in[2];
    float* out = (float*)d_out;

    static int attr_set = 0;
    if (!attr_set) {
        cudaFuncSetAttribute(fused_kernel,
                             cudaFuncAttributeMaxDynamicSharedMemorySize, SMEM_DYN);
        attr_set = 1;
    }

    const int N4 = NROWS * DIM / 4;                 // per tensor
    const int conv_ctas = (3 * N4 / 2 + 255) / 256; // 2 float4 per thread
    convert_kernel<<<conv_ctas, 256>>>((const float4*)O, (const float4*)P,
                                       (const float4*)Ng);
    fused_kernel<<<TOTAL_CTAS, 256, SMEM_DYN>>>(O, P, out);
}